// round 4
// baseline (speedup 1.0000x reference)
#include <cuda_runtime.h>

typedef unsigned long long ULL;

constexpr int TT = 512;   // seq
constexpr int BB = 64;    // batch
constexpr int EE = 256;   // embed
constexpr int HH = 256;   // hidden
constexpr int G4 = 1024;  // 4*H
constexpr int DD2 = 512;  // 2*H
constexpr int NCLS = 5;

// ---------------- device scratch (no allocs allowed) ----------------
__device__ float g_xg[2][TT][G4][BB];    // input-gate preactivations  (268 MB)
__device__ float g_out[TT][DD2][BB];     // biLSTM outputs             (64 MB)
__device__ float g_h[2][2][8][HH][8];    // h double buffer [buf][dir][bg][j][bl]
__device__ float g_plog[4][TT * BB];     // partial attention logits per e-tile
__device__ float g_logit[TT * BB];
__device__ float g_attn[TT * BB];
__device__ float g_vec[BB][DD2];

// ---------------- packed f32x2 helpers (sm_100+) ----------------
__device__ __forceinline__ ULL pk(float lo, float hi) {
    ULL r; asm("mov.b64 %0,{%1,%2};" : "=l"(r) : "f"(lo), "f"(hi)); return r;
}
__device__ __forceinline__ ULL pk2(float x) {
    ULL r; asm("mov.b64 %0,{%1,%1};" : "=l"(r) : "f"(x)); return r;
}
__device__ __forceinline__ void fma2(ULL& d, ULL a, ULL b) {
    asm("fma.rn.f32x2 %0,%1,%2,%0;" : "+l"(d) : "l"(a), "l"(b));
}
__device__ __forceinline__ ULL add2(ULL a, ULL b) {
    ULL r; asm("add.rn.f32x2 %0,%1,%2;" : "=l"(r) : "l"(a), "l"(b)); return r;
}
__device__ __forceinline__ float2 upk(ULL v) {
    float2 r; asm("mov.b64 {%0,%1},%2;" : "=f"(r.x), "=f"(r.y) : "l"(v)); return r;
}
__device__ __forceinline__ float sigf(float x) { return 1.0f / (1.0f + expf(-x)); }

__device__ __forceinline__ void cluster_sync_() {
    asm volatile("barrier.cluster.arrive.aligned;" ::: "memory");
    asm volatile("barrier.cluster.wait.aligned;" ::: "memory");
}

// =====================================================================
// K1: xg[d][t][g][b] = Wih_d @ emb_table[embed[t]]^T + bih + bhh
// grid (8 gate-tiles, T, 2 dirs), 256 thr, tile 128x64, K=256
// =====================================================================
__global__ void __launch_bounds__(256) k1_xg(
    const int* __restrict__ embed, const float* __restrict__ emb_table,
    const float* __restrict__ Wih_f, const float* __restrict__ bih_f, const float* __restrict__ bhh_f,
    const float* __restrict__ Wih_b, const float* __restrict__ bih_b, const float* __restrict__ bhh_b)
{
    const int gt = blockIdx.x;
    const int t  = blockIdx.y;
    const int d  = blockIdx.z;
    const float* Wih = d ? Wih_b : Wih_f;
    const float* bi  = d ? bih_b : bih_f;
    const float* bh  = d ? bhh_b : bhh_f;

    __shared__ float A[32][132];   // [k][row]
    __shared__ float X[32][64];    // [k][b]
    __shared__ int   idx[64];

    const int tid = threadIdx.x;
    if (tid < 64) idx[tid] = embed[t * BB + tid];

    const int g0 = gt * 128;
    const int ty = tid >> 4;   // 0..15 -> 8 rows at ty*8
    const int tx = tid & 15;   // 0..15 -> 4 batches at tx*4

    ULL acc[4][4];
#pragma unroll
    for (int gp = 0; gp < 4; gp++) {
        int r = g0 + ty * 8 + gp * 2;
        ULL bbv = pk(bi[r] + bh[r], bi[r + 1] + bh[r + 1]);
#pragma unroll
        for (int j = 0; j < 4; j++) acc[gp][j] = bbv;
    }

    for (int kt = 0; kt < 8; kt++) {
        const int k0 = kt * 32;
        __syncthreads();
        {   // W tile -> A[k][r] (transposed)
            int r  = tid >> 1;
            int kk = (tid & 1) * 16;
            const float4* src = (const float4*)(Wih + (g0 + r) * EE + k0 + kk);
#pragma unroll
            for (int qq = 0; qq < 4; qq++) {
                float4 v = src[qq];
                A[kk + qq * 4 + 0][r] = v.x;
                A[kk + qq * 4 + 1][r] = v.y;
                A[kk + qq * 4 + 2][r] = v.z;
                A[kk + qq * 4 + 3][r] = v.w;
            }
        }
        {   // X tile: gather embeddings -> X[k][b]
            int b  = tid >> 2;
            int kk = (tid & 3) * 8;
            const float* er = emb_table + (long long)idx[b] * EE + k0 + kk;
            float4 v0 = *(const float4*)(er);
            float4 v1 = *(const float4*)(er + 4);
            X[kk + 0][b] = v0.x; X[kk + 1][b] = v0.y; X[kk + 2][b] = v0.z; X[kk + 3][b] = v0.w;
            X[kk + 4][b] = v1.x; X[kk + 5][b] = v1.y; X[kk + 6][b] = v1.z; X[kk + 7][b] = v1.w;
        }
        __syncthreads();
#pragma unroll
        for (int k = 0; k < 32; k++) {
            float4 w0 = *(const float4*)&A[k][ty * 8];
            float4 w1 = *(const float4*)&A[k][ty * 8 + 4];
            ULL wp0 = pk(w0.x, w0.y), wp1 = pk(w0.z, w0.w);
            ULL wp2 = pk(w1.x, w1.y), wp3 = pk(w1.z, w1.w);
            float4 xv = *(const float4*)&X[k][tx * 4];
            ULL x0 = pk2(xv.x), x1 = pk2(xv.y), x2 = pk2(xv.z), x3 = pk2(xv.w);
            fma2(acc[0][0], wp0, x0); fma2(acc[0][1], wp0, x1); fma2(acc[0][2], wp0, x2); fma2(acc[0][3], wp0, x3);
            fma2(acc[1][0], wp1, x0); fma2(acc[1][1], wp1, x1); fma2(acc[1][2], wp1, x2); fma2(acc[1][3], wp1, x3);
            fma2(acc[2][0], wp2, x0); fma2(acc[2][1], wp2, x1); fma2(acc[2][2], wp2, x2); fma2(acc[2][3], wp2, x3);
            fma2(acc[3][0], wp3, x0); fma2(acc[3][1], wp3, x1); fma2(acc[3][2], wp3, x2); fma2(acc[3][3], wp3, x3);
        }
    }

    float* dst = &g_xg[d][t][0][0];
#pragma unroll
    for (int gp = 0; gp < 4; gp++) {
        int r = g0 + ty * 8 + gp * 2;
        float2 a0 = upk(acc[gp][0]), a1 = upk(acc[gp][1]), a2 = upk(acc[gp][2]), a3 = upk(acc[gp][3]);
        *(float4*)&dst[r * BB + tx * 4]       = make_float4(a0.x, a1.x, a2.x, a3.x);
        *(float4*)&dst[(r + 1) * BB + tx * 4] = make_float4(a0.y, a1.y, a2.y, a3.y);
    }
}

// =====================================================================
// K2: persistent biLSTM recurrence. 128 CTAs = 2 dirs x 8 batch-groups x
// 8 hidden-groups; each batch-group is an 8-CTA cluster (the only sync scope).
// Whh slice register-resident. 512 threads: (row r in [0,128), k-quarter q).
// h exchange via L2 (__stcg/__ldcg), ordered by the cluster barrier.
// =====================================================================
__global__ void __launch_bounds__(512, 1) __cluster_dims__(8, 1, 1)
k2_rnn(const float* __restrict__ h0, const float* __restrict__ c0,
       const float* __restrict__ Whh_f, const float* __restrict__ Whh_b)
{
    __shared__ __align__(16) float h_sm[2048];   // [j 0..255][bl 0..7]
    __shared__ float gsm[1024];                  // [gate][jl][bl]
    __shared__ float csm[256];                   // [jl][bl]

    const int bid = blockIdx.x;
    const int hg = bid & 7;
    const int bg = (bid >> 3) & 7;
    const int d  = bid >> 6;
    const int tid = threadIdx.x;
    const int r = tid >> 2, q = tid & 3;         // r: row in CTA, q: k-quarter
    const int gate = r >> 5, jl = r & 31;
    const int grow = gate * 256 + hg * 32 + jl;  // global gate-row
    const float* Whh = d ? Whh_b : Whh_f;

    // register-resident Whh slice: row grow, k in [q*64, q*64+64)
    float w[64];
    {
        const float4* ws = (const float4*)(Whh + grow * HH + q * 64);
#pragma unroll
        for (int i = 0; i < 16; i++) {
            float4 v = ws[i];
            w[4 * i] = v.x; w[4 * i + 1] = v.y; w[4 * i + 2] = v.z; w[4 * i + 3] = v.w;
        }
    }

    if (tid < 256) {
        int cj = tid >> 3, cb = tid & 7;
        int b = bg * 8 + cb, j = hg * 32 + cj;
        csm[cj * 8 + cb] = c0[(d * BB + b) * HH + j];
        __stcg(&g_h[0][d][bg][j][cb], h0[(d * BB + b) * HH + j]);
    }
    cluster_sync_();

    int p = 0;
    for (int s = 0; s < TT; s++) {
        const int t = d ? (TT - 1 - s) : s;

        float4 xa, xb;
        if (q == 0) {   // prefetch this row's xg for its 8 batches
            const float4* xgp = (const float4*)&g_xg[d][t][grow][bg * 8];
            xa = xgp[0]; xb = xgp[1];
        }
        {   // stage h_prev (8 KB) into smem (L2 -> smem, bypass L1)
            const float4* hs = (const float4*)&g_h[p][d][bg][0][0];
            ((float4*)h_sm)[tid] = __ldcg(hs + tid);
        }
        __syncthreads();

        ULL a01, a23, a45, a67;
        if (q == 0) {
            a01 = pk(xa.x, xa.y); a23 = pk(xa.z, xa.w);
            a45 = pk(xb.x, xb.y); a67 = pk(xb.z, xb.w);
        } else {
            a01 = a23 = a45 = a67 = 0ull;
        }

        const ulonglong2* hb = (const ulonglong2*)(h_sm + q * 64 * 8);
#pragma unroll
        for (int k = 0; k < 64; k++) {
            ULL w2 = pk2(w[k]);
            ulonglong2 hA = hb[2 * k], hB = hb[2 * k + 1];
            fma2(a01, w2, hA.x); fma2(a23, w2, hA.y);
            fma2(a45, w2, hB.x); fma2(a67, w2, hB.y);
        }
        // reduce across the 4 k-quarters (lanes xor 1, 2)
        a01 = add2(a01, __shfl_xor_sync(0xffffffffu, a01, 1));
        a01 = add2(a01, __shfl_xor_sync(0xffffffffu, a01, 2));
        a23 = add2(a23, __shfl_xor_sync(0xffffffffu, a23, 1));
        a23 = add2(a23, __shfl_xor_sync(0xffffffffu, a23, 2));
        a45 = add2(a45, __shfl_xor_sync(0xffffffffu, a45, 1));
        a45 = add2(a45, __shfl_xor_sync(0xffffffffu, a45, 2));
        a67 = add2(a67, __shfl_xor_sync(0xffffffffu, a67, 1));
        a67 = add2(a67, __shfl_xor_sync(0xffffffffu, a67, 2));

        float* gr = &gsm[gate * 256 + jl * 8];
        if (q == 0)      { float2 v = upk(a01); gr[0] = v.x; gr[1] = v.y; }
        else if (q == 1) { float2 v = upk(a23); gr[2] = v.x; gr[3] = v.y; }
        else if (q == 2) { float2 v = upk(a45); gr[4] = v.x; gr[5] = v.y; }
        else             { float2 v = upk(a67); gr[6] = v.x; gr[7] = v.y; }
        __syncthreads();

        if (tid < 256) {
            int cj = tid >> 3, cb = tid & 7;
            float gi = gsm[cj * 8 + cb];
            float gf = gsm[256 + cj * 8 + cb];
            float gg = gsm[512 + cj * 8 + cb];
            float go = gsm[768 + cj * 8 + cb];
            float c = csm[cj * 8 + cb];
            c = sigf(gf) * c + sigf(gi) * tanhf(gg);
            float h = sigf(go) * tanhf(c);
            csm[cj * 8 + cb] = c;
            __stcg(&g_h[p ^ 1][d][bg][hg * 32 + cj][cb], h);
            g_out[t][d * 256 + hg * 32 + cj][bg * 8 + cb] = h;
        }
        cluster_sync_();
        p ^= 1;
    }
}

// =====================================================================
// K3a: partial attention logits.
// plog[et][t][b] = sum_{e in tile} tanh((out[t,b,:]@W_word)[e]+b_word[e])*proj[e]
// grid (4 e-tiles, T), tile 128x64, K=512
// =====================================================================
__global__ void __launch_bounds__(256) k3a_logits(
    const float* __restrict__ W_word, const float* __restrict__ b_word,
    const float* __restrict__ proj)
{
    const int et = blockIdx.x;
    const int t  = blockIdx.y;
    __shared__ float Bs[32][132];   // [k][e]
    __shared__ float Xs[32][64];    // [k][b]
    __shared__ float red[64][17];

    const int tid = threadIdx.x;
    const int ty = tid >> 4, tx = tid & 15;
    const int e0 = et * 128;

    ULL acc[4][4];
#pragma unroll
    for (int gp = 0; gp < 4; gp++)
#pragma unroll
        for (int j = 0; j < 4; j++) acc[gp][j] = 0ull;

    for (int kt = 0; kt < 16; kt++) {
        const int k0 = kt * 32;
        __syncthreads();
        {   // W_word tile (already [d][e] = [k][e], no transpose)
            int k  = tid >> 3;
            int ec = (tid & 7) * 16;
            const float4* src = (const float4*)(W_word + (k0 + k) * DD2 + e0 + ec);
#pragma unroll
            for (int qq = 0; qq < 4; qq++)
                *(float4*)&Bs[k][ec + qq * 4] = src[qq];
        }
        {   // out tile: g_out[t][k][b], b contiguous
            int k  = tid >> 3;
            int bc = (tid & 7) * 8;
            const float4* src = (const float4*)&g_out[t][k0 + k][bc];
            *(float4*)&Xs[k][bc]     = src[0];
            *(float4*)&Xs[k][bc + 4] = src[1];
        }
        __syncthreads();
#pragma unroll
        for (int k = 0; k < 32; k++) {
            float4 w0 = *(const float4*)&Bs[k][ty * 8];
            float4 w1 = *(const float4*)&Bs[k][ty * 8 + 4];
            ULL wp0 = pk(w0.x, w0.y), wp1 = pk(w0.z, w0.w);
            ULL wp2 = pk(w1.x, w1.y), wp3 = pk(w1.z, w1.w);
            float4 xv = *(const float4*)&Xs[k][tx * 4];
            ULL x0 = pk2(xv.x), x1 = pk2(xv.y), x2 = pk2(xv.z), x3 = pk2(xv.w);
            fma2(acc[0][0], wp0, x0); fma2(acc[0][1], wp0, x1); fma2(acc[0][2], wp0, x2); fma2(acc[0][3], wp0, x3);
            fma2(acc[1][0], wp1, x0); fma2(acc[1][1], wp1, x1); fma2(acc[1][2], wp1, x2); fma2(acc[1][3], wp1, x3);
            fma2(acc[2][0], wp2, x0); fma2(acc[2][1], wp2, x1); fma2(acc[2][2], wp2, x2); fma2(acc[2][3], wp2, x3);
            fma2(acc[3][0], wp3, x0); fma2(acc[3][1], wp3, x1); fma2(acc[3][2], wp3, x2); fma2(acc[3][3], wp3, x3);
        }
    }

    // finalize: tanh(+bias)*proj, reduce over this thread's 8 e-rows
    float part[4] = {0.f, 0.f, 0.f, 0.f};
#pragma unroll
    for (int gp = 0; gp < 4; gp++) {
        int e = e0 + ty * 8 + gp * 2;
        float bw0 = b_word[e], bw1 = b_word[e + 1];
        float pw0 = proj[e],   pw1 = proj[e + 1];
#pragma unroll
        for (int j = 0; j < 4; j++) {
            float2 a = upk(acc[gp][j]);
            part[j] += tanhf(a.x + bw0) * pw0 + tanhf(a.y + bw1) * pw1;
        }
    }
#pragma unroll
    for (int j = 0; j < 4; j++) red[tx * 4 + j][ty] = part[j];
    __syncthreads();
    if (tid < 64) {
        float s = 0.f;
#pragma unroll
        for (int i = 0; i < 16; i++) s += red[tid][i];
        g_plog[et][t * BB + tid] = s;
    }
}

// =====================================================================
// K3b1: softmax over T per batch
// =====================================================================
__global__ void __launch_bounds__(256) k3b1_softmax()
{
    __shared__ float red[4][64];
    const int tid = threadIdx.x;
    const int part = tid >> 6, b = tid & 63;

    float m = -1e30f;
    for (int i = 0; i < 128; i++) {
        int o = (part * 128 + i) * BB + b;
        float l = g_plog[0][o] + g_plog[1][o] + g_plog[2][o] + g_plog[3][o];
        g_logit[o] = l;
        m = fmaxf(m, l);
    }
    red[part][b] = m;
    __syncthreads();
    m = fmaxf(fmaxf(red[0][b], red[1][b]), fmaxf(red[2][b], red[3][b]));
    __syncthreads();

    float ssum = 0.f;
    for (int i = 0; i < 128; i++) {
        int o = (part * 128 + i) * BB + b;
        ssum += expf(g_logit[o] - m);
    }
    red[part][b] = ssum;
    __syncthreads();
    ssum = red[0][b] + red[1][b] + red[2][b] + red[3][b];
    float inv = 1.0f / ssum;

    for (int i = 0; i < 128; i++) {
        int o = (part * 128 + i) * BB + b;
        g_attn[o] = expf(g_logit[o] - m) * inv;
    }
}

// =====================================================================
// K3b2: vec[b][d] = sum_t attn[t,b] * out[t,d,b]   (64 CTAs x 8 d-rows)
// =====================================================================
__global__ void __launch_bounds__(256) k3b2_vec()
{
    const int d0 = blockIdx.x * 8;
    const int dl = threadIdx.x >> 5, lane = threadIdx.x & 31;
    const int row = d0 + dl;
    float a0 = 0.f, a1 = 0.f;
#pragma unroll 4
    for (int t = 0; t < TT; t++) {
        float at0 = g_attn[t * BB + lane];
        float at1 = g_attn[t * BB + 32 + lane];
        a0 += at0 * g_out[t][row][lane];
        a1 += at1 * g_out[t][row][32 + lane];
    }
    g_vec[lane][row] = a0;
    g_vec[32 + lane][row] = a1;
}

// =====================================================================
// K3c: final linear  out[b][n] = vec[b,:] . lin_W[n,:] + lin_b[n]
// =====================================================================
__global__ void __launch_bounds__(512) k3c_final(
    const float* __restrict__ lin_W, const float* __restrict__ lin_b,
    float* __restrict__ out)
{
    const int wid = threadIdx.x >> 5, lane = threadIdx.x & 31;
    for (int i = 0; i < 20; i++) {
        int o = wid * 20 + i;           // 16 warps * 20 = 320 outputs
        int b = o / NCLS, n = o % NCLS;
        float s = 0.f;
#pragma unroll
        for (int j = 0; j < 16; j++) {
            int dd = lane + 32 * j;
            s += g_vec[b][dd] * lin_W[n * DD2 + dd];
        }
#pragma unroll
        for (int off = 16; off; off >>= 1)
            s += __shfl_xor_sync(0xffffffffu, s, off);
        if (lane == 0) out[b * NCLS + n] = s + lin_b[n];
    }
}

// =====================================================================
extern "C" void kernel_launch(void* const* d_in, const int* in_sizes, int n_in,
                              void* d_out, int out_size)
{
    const int*   embed     = (const int*)  d_in[0];
    const float* h0        = (const float*)d_in[1];
    const float* c0        = (const float*)d_in[2];
    const float* emb_table = (const float*)d_in[3];
    const float* Wih_f     = (const float*)d_in[4];
    const float* Whh_f     = (const float*)d_in[5];
    const float* bih_f     = (const float*)d_in[6];
    const float* bhh_f     = (const float*)d_in[7];
    const float* Wih_b     = (const float*)d_in[8];
    const float* Whh_b     = (const float*)d_in[9];
    const float* bih_b     = (const float*)d_in[10];
    const float* bhh_b     = (const float*)d_in[11];
    const float* W_word    = (const float*)d_in[12];
    const float* b_word    = (const float*)d_in[13];
    const float* proj_word = (const float*)d_in[14];
    const float* lin_W     = (const float*)d_in[15];
    const float* lin_b     = (const float*)d_in[16];
    float* out = (float*)d_out;

    k1_xg<<<dim3(8, TT, 2), 256>>>(embed, emb_table,
                                   Wih_f, bih_f, bhh_f,
                                   Wih_b, bih_b, bhh_b);
    k2_rnn<<<128, 512>>>(h0, c0, Whh_f, Whh_b);
    k3a_logits<<<dim3(4, TT), 256>>>(W_word, b_word, proj_word);
    k3b1_softmax<<<1, 256>>>();
    k3b2_vec<<<64, 256>>>();
    k3c_final<<<1, 512>>>(lin_W, lin_b, out);
}

// round 7
// speedup vs baseline: 2.5242x; 2.5242x over previous
#include <cuda_runtime.h>

typedef unsigned long long ULL;

constexpr int TT = 512;   // seq
constexpr int BB = 64;    // batch
constexpr int EE = 256;   // embed
constexpr int HH = 256;   // hidden
constexpr int G4 = 1024;  // 4*H
constexpr int DD2 = 512;  // 2*H
constexpr int NCLS = 5;

// ---------------- device scratch (no allocs allowed) ----------------
__device__ float g_xg[2][TT][G4][BB];    // input-gate preactivations  (268 MB)
__device__ float g_out[TT][DD2][BB];     // biLSTM outputs             (64 MB)
__device__ float g_h[2][2][4][HH][16];   // h double buffer [buf][dir][bg][j][bl]
__device__ float g_plog[4][TT * BB];     // partial attention logits per e-tile
__device__ float g_attn[TT * BB];
__device__ float g_vec[BB][DD2];
__device__ float g_dummy[32];

// per-group barrier state: 8 groups of 8 CTAs
__device__ unsigned g_cnt[8];            // zero-init, returns to 0 every barrier
__device__ volatile unsigned g_flag[8];  // zero-init, monotonically increasing (replay-safe)

// ---------------- packed f32x2 helpers (sm_100+) ----------------
__device__ __forceinline__ ULL pk(float lo, float hi) {
    ULL r; asm("mov.b64 %0,{%1,%2};" : "=l"(r) : "f"(lo), "f"(hi)); return r;
}
__device__ __forceinline__ ULL pk2(float x) {
    ULL r; asm("mov.b64 %0,{%1,%1};" : "=l"(r) : "f"(x)); return r;
}
__device__ __forceinline__ void fma2(ULL& d, ULL a, ULL b) {
    asm("fma.rn.f32x2 %0,%1,%2,%0;" : "+l"(d) : "l"(a), "l"(b));
}
__device__ __forceinline__ ULL add2(ULL a, ULL b) {
    ULL r; asm("add.rn.f32x2 %0,%1,%2;" : "=l"(r) : "l"(a), "l"(b)); return r;
}
__device__ __forceinline__ float2 upk(ULL v) {
    float2 r; asm("mov.b64 {%0,%1},%2;" : "=f"(r.x), "=f"(r.y) : "l"(v)); return r;
}
__device__ __forceinline__ float sigf(float x) { return 1.0f / (1.0f + expf(-x)); }

// sense-reversing barrier over the 8 CTAs of group gidx
__device__ __forceinline__ void group_sync(int gidx) {
    __threadfence();              // make this thread's global stores visible
    __syncthreads();              // all threads' fences done before leader arrives
    if (threadIdx.x == 0) {
        unsigned ph = g_flag[gidx];
        if (atomicAdd(&g_cnt[gidx], 1u) == 7u) {
            g_cnt[gidx] = 0u;     // safe: all 8 arrived, none re-arrive until flag flips
            __threadfence();
            g_flag[gidx] = ph + 1u;
        } else {
            while (g_flag[gidx] == ph) { __nanosleep(32); }
        }
        __threadfence();
    }
    __syncthreads();
}

// =====================================================================
// K1: xg[d][t][g][b] = Wih_d @ emb_table[embed[t]]^T + bih + bhh
// one launch per direction; grid (8 gate-tiles, T), 256 thr, tile 128x64
// =====================================================================
__global__ void __launch_bounds__(256) k1_xg(
    int d, const int* __restrict__ embed, const float* __restrict__ emb_table,
    const float* __restrict__ Wih, const float* __restrict__ bi, const float* __restrict__ bh)
{
    const int gt = blockIdx.x;
    const int t  = blockIdx.y;

    __shared__ float A[32][132];   // [k][row]
    __shared__ float X[32][64];    // [k][b]
    __shared__ int   idx[64];

    const int tid = threadIdx.x;
    if (tid < 64) idx[tid] = embed[t * BB + tid];

    const int g0 = gt * 128;
    const int ty = tid >> 4;   // 0..15 -> 8 rows at ty*8
    const int tx = tid & 15;   // 0..15 -> 4 batches at tx*4

    ULL acc[4][4];
#pragma unroll
    for (int gp = 0; gp < 4; gp++) {
        int r = g0 + ty * 8 + gp * 2;
        ULL bbv = pk(bi[r] + bh[r], bi[r + 1] + bh[r + 1]);
#pragma unroll
        for (int j = 0; j < 4; j++) acc[gp][j] = bbv;
    }

    for (int kt = 0; kt < 8; kt++) {
        const int k0 = kt * 32;
        __syncthreads();
        {   // W tile -> A[k][r] (transposed)
            int r  = tid >> 1;
            int kk = (tid & 1) * 16;
            const float4* src = (const float4*)(Wih + (g0 + r) * EE + k0 + kk);
#pragma unroll
            for (int qq = 0; qq < 4; qq++) {
                float4 v = src[qq];
                A[kk + qq * 4 + 0][r] = v.x;
                A[kk + qq * 4 + 1][r] = v.y;
                A[kk + qq * 4 + 2][r] = v.z;
                A[kk + qq * 4 + 3][r] = v.w;
            }
        }
        {   // X tile: gather embeddings -> X[k][b]
            int b  = tid >> 2;
            int kk = (tid & 3) * 8;
            const float* er = emb_table + (long long)idx[b] * EE + k0 + kk;
            float4 v0 = *(const float4*)(er);
            float4 v1 = *(const float4*)(er + 4);
            X[kk + 0][b] = v0.x; X[kk + 1][b] = v0.y; X[kk + 2][b] = v0.z; X[kk + 3][b] = v0.w;
            X[kk + 4][b] = v1.x; X[kk + 5][b] = v1.y; X[kk + 6][b] = v1.z; X[kk + 7][b] = v1.w;
        }
        __syncthreads();
#pragma unroll
        for (int k = 0; k < 32; k++) {
            float4 w0 = *(const float4*)&A[k][ty * 8];
            float4 w1 = *(const float4*)&A[k][ty * 8 + 4];
            ULL wp0 = pk(w0.x, w0.y), wp1 = pk(w0.z, w0.w);
            ULL wp2 = pk(w1.x, w1.y), wp3 = pk(w1.z, w1.w);
            float4 xv = *(const float4*)&X[k][tx * 4];
            ULL x0 = pk2(xv.x), x1 = pk2(xv.y), x2 = pk2(xv.z), x3 = pk2(xv.w);
            fma2(acc[0][0], wp0, x0); fma2(acc[0][1], wp0, x1); fma2(acc[0][2], wp0, x2); fma2(acc[0][3], wp0, x3);
            fma2(acc[1][0], wp1, x0); fma2(acc[1][1], wp1, x1); fma2(acc[1][2], wp1, x2); fma2(acc[1][3], wp1, x3);
            fma2(acc[2][0], wp2, x0); fma2(acc[2][1], wp2, x1); fma2(acc[2][2], wp2, x2); fma2(acc[2][3], wp2, x3);
            fma2(acc[3][0], wp3, x0); fma2(acc[3][1], wp3, x1); fma2(acc[3][2], wp3, x2); fma2(acc[3][3], wp3, x3);
        }
    }

    float* dst = &g_xg[d][t][0][0];
#pragma unroll
    for (int gp = 0; gp < 4; gp++) {
        int r = g0 + ty * 8 + gp * 2;
        float2 a0 = upk(acc[gp][0]), a1 = upk(acc[gp][1]), a2 = upk(acc[gp][2]), a3 = upk(acc[gp][3]);
        __stcs((float4*)&dst[r * BB + tx * 4],       make_float4(a0.x, a1.x, a2.x, a3.x));
        __stcs((float4*)&dst[(r + 1) * BB + tx * 4], make_float4(a0.y, a1.y, a2.y, a3.y));
    }
}

// pad kernel (keeps K2 at captured launch index 3)
__global__ void k_pad() { if (threadIdx.x == 0) g_dummy[0] = 0.f; }

// =====================================================================
// K2: persistent biLSTM recurrence, NO clusters, 64 CTAs (co-residency-safe).
// 64 CTAs = 2 dirs x 4 batch-groups(16 batches) x 8 hidden-groups(32 hidden).
// The 8 CTAs sharing (dir,bg) sync via a private atomic barrier.
// Whh slice register-resident: thread = (gate-row r in [0,128), k-quarter q),
// w[64] = row grow, k in [q*64,(q+1)*64). 8 f32x2 accs = 16 batches.
// =====================================================================
constexpr int HQ = 1028;                   // padded quarter stride (floats)

__global__ void __launch_bounds__(512, 1)
k2_rnn(const float* __restrict__ h0, const float* __restrict__ c0,
       const float* __restrict__ Whh_f, const float* __restrict__ Whh_b)
{
    __shared__ __align__(16) float h_sm[4 * HQ]; // 4 padded k-quarters of [k][bl=16]
    __shared__ float gsm[2048];                  // [gate][jl][bl] 8KB
    __shared__ float csm[512];                   // [jl][bl] 2KB

    const int bid = blockIdx.x;                  // 0..63
    const int hg = bid & 7;
    const int bg = (bid >> 3) & 3;
    const int d  = bid >> 5;
    const int gid = bid >> 3;                    // group 0..7
    const int tid = threadIdx.x;
    const int r = tid >> 2, q = tid & 3;         // r: gate-row in CTA, q: k-quarter
    const int gate = r >> 5, jl = r & 31;
    const int grow = gate * 256 + hg * 32 + jl;  // global gate-row
    const float* Whh = d ? Whh_b : Whh_f;

    // register-resident Whh slice
    float w[64];
    {
        const float4* ws = (const float4*)(Whh + grow * HH + q * 64);
#pragma unroll
        for (int i = 0; i < 16; i++) {
            float4 v = ws[i];
            w[4 * i] = v.x; w[4 * i + 1] = v.y; w[4 * i + 2] = v.z; w[4 * i + 3] = v.w;
        }
    }

    {   // init state: 512 threads = 32 jl x 16 bl
        int cj = tid >> 4, cb = tid & 15;
        int b = bg * 16 + cb, j = hg * 32 + cj;
        csm[cj * 16 + cb] = c0[(d * BB + b) * HH + j];
        __stcg(&g_h[0][d][bg][j][cb], h0[(d * BB + b) * HH + j]);
    }
    group_sync(gid);

    int p = 0;
    for (int s = 0; s < TT; s++) {
        const int t = d ? (TT - 1 - s) : s;

        // xg prefetch: lane q loads its 4 batches of this row (streaming)
        float4 xv = __ldcs((const float4*)&g_xg[d][t][grow][bg * 16] + q);

        {   // stage h_prev (16 KB) into padded smem quarters (L2 -> smem)
            const float4* hs = (const float4*)&g_h[p][d][bg][0][0];
#pragma unroll
            for (int i = 0; i < 2; i++) {
                int v4 = tid + i * 512;              // float4 index, 0..1023
                int f  = v4 * 4;                     // source float index
                float4 val = __ldcg(hs + v4);
                *(float4*)&h_sm[(f >> 10) * HQ + (f & 1023)] = val;
            }
        }
        __syncthreads();

        ULL acc[8];
#pragma unroll
        for (int i = 0; i < 8; i++) acc[i] = 0ull;

        const ulonglong2* hb = (const ulonglong2*)(h_sm + q * HQ);
#pragma unroll 8
        for (int k = 0; k < 64; k++) {
            ULL w2 = pk2(w[k]);
            ulonglong2 hA = hb[4 * k + 0], hB = hb[4 * k + 1];
            ulonglong2 hC = hb[4 * k + 2], hD = hb[4 * k + 3];
            fma2(acc[0], w2, hA.x); fma2(acc[1], w2, hA.y);
            fma2(acc[2], w2, hB.x); fma2(acc[3], w2, hB.y);
            fma2(acc[4], w2, hC.x); fma2(acc[5], w2, hC.y);
            fma2(acc[6], w2, hD.x); fma2(acc[7], w2, hD.y);
        }
        // reduce across the 4 k-quarter lanes (same r: lanes xor 1, 2)
#pragma unroll
        for (int i = 0; i < 8; i++) {
            acc[i] = add2(acc[i], __shfl_xor_sync(0xffffffffu, acc[i], 1));
            acc[i] = add2(acc[i], __shfl_xor_sync(0xffffffffu, acc[i], 2));
        }
        // lane q owns batches [4q,4q+4): add its xg, store to gsm
        {
            float2 p0 = upk(acc[2 * q]), p1 = upk(acc[2 * q + 1]);
            *(float4*)&gsm[gate * 512 + jl * 16 + q * 4] =
                make_float4(p0.x + xv.x, p0.y + xv.y, p1.x + xv.z, p1.y + xv.w);
        }
        __syncthreads();

        {   // tail: all 512 threads, one (j,b) each
            int cj = tid >> 4, cb = tid & 15;
            int o = cj * 16 + cb;
            float gi = gsm[o];
            float gf = gsm[512 + o];
            float gg = gsm[1024 + o];
            float go = gsm[1536 + o];
            float c = csm[o];
            c = sigf(gf) * c + sigf(gi) * tanhf(gg);
            float h = sigf(go) * tanhf(c);
            csm[o] = c;
            __stcg(&g_h[p ^ 1][d][bg][hg * 32 + cj][cb], h);
            g_out[t][d * 256 + hg * 32 + cj][bg * 16 + cb] = h;
        }
        group_sync(gid);
        p ^= 1;
    }
}

// =====================================================================
// K3a: partial attention logits.
// plog[et][t][b] = sum_{e in tile} tanh((out[t,b,:]@W_word)[e]+b_word[e])*proj[e]
// grid (4 e-tiles, T), tile 128x64, K=512
// =====================================================================
__global__ void __launch_bounds__(256) k3a_logits(
    const float* __restrict__ W_word, const float* __restrict__ b_word,
    const float* __restrict__ proj)
{
    const int et = blockIdx.x;
    const int t  = blockIdx.y;
    __shared__ float Bs[32][132];   // [k][e]
    __shared__ float Xs[32][64];    // [k][b]
    __shared__ float red[64][17];

    const int tid = threadIdx.x;
    const int ty = tid >> 4, tx = tid & 15;
    const int e0 = et * 128;

    ULL acc[4][4];
#pragma unroll
    for (int gp = 0; gp < 4; gp++)
#pragma unroll
        for (int j = 0; j < 4; j++) acc[gp][j] = 0ull;

    for (int kt = 0; kt < 16; kt++) {
        const int k0 = kt * 32;
        __syncthreads();
        {   // W_word tile (already [d][e] = [k][e], no transpose)
            int k  = tid >> 3;
            int ec = (tid & 7) * 16;
            const float4* src = (const float4*)(W_word + (k0 + k) * DD2 + e0 + ec);
#pragma unroll
            for (int qq = 0; qq < 4; qq++)
                *(float4*)&Bs[k][ec + qq * 4] = src[qq];
        }
        {   // out tile: g_out[t][k][b], b contiguous
            int k  = tid >> 3;
            int bc = (tid & 7) * 8;
            const float4* src = (const float4*)&g_out[t][k0 + k][bc];
            *(float4*)&Xs[k][bc]     = src[0];
            *(float4*)&Xs[k][bc + 4] = src[1];
        }
        __syncthreads();
#pragma unroll
        for (int k = 0; k < 32; k++) {
            float4 w0 = *(const float4*)&Bs[k][ty * 8];
            float4 w1 = *(const float4*)&Bs[k][ty * 8 + 4];
            ULL wp0 = pk(w0.x, w0.y), wp1 = pk(w0.z, w0.w);
            ULL wp2 = pk(w1.x, w1.y), wp3 = pk(w1.z, w1.w);
            float4 xv = *(const float4*)&Xs[k][tx * 4];
            ULL x0 = pk2(xv.x), x1 = pk2(xv.y), x2 = pk2(xv.z), x3 = pk2(xv.w);
            fma2(acc[0][0], wp0, x0); fma2(acc[0][1], wp0, x1); fma2(acc[0][2], wp0, x2); fma2(acc[0][3], wp0, x3);
            fma2(acc[1][0], wp1, x0); fma2(acc[1][1], wp1, x1); fma2(acc[1][2], wp1, x2); fma2(acc[1][3], wp1, x3);
            fma2(acc[2][0], wp2, x0); fma2(acc[2][1], wp2, x1); fma2(acc[2][2], wp2, x2); fma2(acc[2][3], wp2, x3);
            fma2(acc[3][0], wp3, x0); fma2(acc[3][1], wp3, x1); fma2(acc[3][2], wp3, x2); fma2(acc[3][3], wp3, x3);
        }
    }

    // finalize: tanh(+bias)*proj, reduce over this thread's 8 e-rows
    float part[4] = {0.f, 0.f, 0.f, 0.f};
#pragma unroll
    for (int gp = 0; gp < 4; gp++) {
        int e = e0 + ty * 8 + gp * 2;
        float bw0 = b_word[e], bw1 = b_word[e + 1];
        float pw0 = proj[e],   pw1 = proj[e + 1];
#pragma unroll
        for (int j = 0; j < 4; j++) {
            float2 a = upk(acc[gp][j]);
            part[j] += tanhf(a.x + bw0) * pw0 + tanhf(a.y + bw1) * pw1;
        }
    }
#pragma unroll
    for (int j = 0; j < 4; j++) red[tx * 4 + j][ty] = part[j];
    __syncthreads();
    if (tid < 64) {
        float s = 0.f;
#pragma unroll
        for (int i = 0; i < 16; i++) s += red[tid][i];
        g_plog[et][t * BB + tid] = s;
    }
}

// =====================================================================
// K3b1: softmax over T per batch. One CTA per batch (64 CTAs, 256 thr).
// =====================================================================
__global__ void __launch_bounds__(256) k3b1_softmax()
{
    __shared__ float red[8];
    const int b = blockIdx.x;
    const int tid = threadIdx.x;
    const int wid = tid >> 5, lane = tid & 31;

    const int o0 = tid * BB + b, o1 = (tid + 256) * BB + b;
    float l0 = g_plog[0][o0] + g_plog[1][o0] + g_plog[2][o0] + g_plog[3][o0];
    float l1 = g_plog[0][o1] + g_plog[1][o1] + g_plog[2][o1] + g_plog[3][o1];

    float m = fmaxf(l0, l1);
#pragma unroll
    for (int off = 16; off; off >>= 1) m = fmaxf(m, __shfl_xor_sync(0xffffffffu, m, off));
    if (lane == 0) red[wid] = m;
    __syncthreads();
    m = red[0];
#pragma unroll
    for (int i = 1; i < 8; i++) m = fmaxf(m, red[i]);
    __syncthreads();

    float e0 = expf(l0 - m), e1 = expf(l1 - m);
    float s = e0 + e1;
#pragma unroll
    for (int off = 16; off; off >>= 1) s += __shfl_xor_sync(0xffffffffu, s, off);
    if (lane == 0) red[wid] = s;
    __syncthreads();
    s = red[0] + red[1] + red[2] + red[3] + red[4] + red[5] + red[6] + red[7];
    float inv = 1.0f / s;

    g_attn[o0] = e0 * inv;
    g_attn[o1] = e1 * inv;
}

// =====================================================================
// K3b2: vec[b][d] = sum_t attn[t,b] * out[t,d,b]   (64 CTAs x 8 d-rows)
// =====================================================================
__global__ void __launch_bounds__(256) k3b2_vec()
{
    const int d0 = blockIdx.x * 8;
    const int dl = threadIdx.x >> 5, lane = threadIdx.x & 31;
    const int row = d0 + dl;
    float a0 = 0.f, a1 = 0.f;
#pragma unroll 4
    for (int t = 0; t < TT; t++) {
        float at0 = g_attn[t * BB + lane];
        float at1 = g_attn[t * BB + 32 + lane];
        a0 += at0 * g_out[t][row][lane];
        a1 += at1 * g_out[t][row][32 + lane];
    }
    g_vec[lane][row] = a0;
    g_vec[32 + lane][row] = a1;
}

// =====================================================================
// K3c: final linear  out[b][n] = vec[b,:] . lin_W[n,:] + lin_b[n]
// =====================================================================
__global__ void __launch_bounds__(512) k3c_final(
    const float* __restrict__ lin_W, const float* __restrict__ lin_b,
    float* __restrict__ out)
{
    const int wid = threadIdx.x >> 5, lane = threadIdx.x & 31;
    for (int i = 0; i < 20; i++) {
        int o = wid * 20 + i;           // 16 warps * 20 = 320 outputs
        int b = o / NCLS, n = o % NCLS;
        float s = 0.f;
#pragma unroll
        for (int j = 0; j < 16; j++) {
            int dd = lane + 32 * j;
            s += g_vec[b][dd] * lin_W[n * DD2 + dd];
        }
#pragma unroll
        for (int off = 16; off; off >>= 1)
            s += __shfl_xor_sync(0xffffffffu, s, off);
        if (lane == 0) out[b * NCLS + n] = s + lin_b[n];
    }
}

// =====================================================================
extern "C" void kernel_launch(void* const* d_in, const int* in_sizes, int n_in,
                              void* d_out, int out_size)
{
    const int*   embed     = (const int*)  d_in[0];
    const float* h0        = (const float*)d_in[1];
    const float* c0        = (const float*)d_in[2];
    const float* emb_table = (const float*)d_in[3];
    const float* Wih_f     = (const float*)d_in[4];
    const float* Whh_f     = (const float*)d_in[5];
    const float* bih_f     = (const float*)d_in[6];
    const float* bhh_f     = (const float*)d_in[7];
    const float* Wih_b     = (const float*)d_in[8];
    const float* Whh_b     = (const float*)d_in[9];
    const float* bih_b     = (const float*)d_in[10];
    const float* bhh_b     = (const float*)d_in[11];
    const float* W_word    = (const float*)d_in[12];
    const float* b_word    = (const float*)d_in[13];
    const float* proj_word = (const float*)d_in[14];
    const float* lin_W     = (const float*)d_in[15];
    const float* lin_b     = (const float*)d_in[16];
    float* out = (float*)d_out;

    k1_xg<<<dim3(8, TT), 256>>>(0, embed, emb_table, Wih_f, bih_f, bhh_f);   // idx 0
    k1_xg<<<dim3(8, TT), 256>>>(1, embed, emb_table, Wih_b, bih_b, bhh_b);   // idx 1
    k_pad<<<1, 32>>>();                                                      // idx 2
    k2_rnn<<<64, 512>>>(h0, c0, Whh_f, Whh_b);                               // idx 3 (capture slot)
    k3a_logits<<<dim3(4, TT), 256>>>(W_word, b_word, proj_word);             // idx 4
    k3b1_softmax<<<64, 256>>>();                                             // idx 5
    k3b2_vec<<<64, 256>>>();                                                 // idx 6
    k3c_final<<<1, 512>>>(lin_W, lin_b, out);                                // idx 7
}

// round 8
// speedup vs baseline: 2.6344x; 1.0437x over previous
#include <cuda_runtime.h>

typedef unsigned long long ULL;

constexpr int TT = 512;   // seq
constexpr int BB = 64;    // batch
constexpr int EE = 256;   // embed
constexpr int HH = 256;   // hidden
constexpr int G4 = 1024;  // 4*H
constexpr int DD2 = 512;  // 2*H
constexpr int NCLS = 5;

// ---------------- device scratch (no allocs allowed) ----------------
__device__ float g_xg[2][TT][G4][BB];    // input-gate preactivations  (268 MB)
__device__ float g_out[TT][DD2][BB];     // biLSTM outputs             (64 MB)
__device__ float g_h[2][2][4][HH][16];   // h double buffer [buf][dir][bg][j][bl]
__device__ float g_plog[4][TT * BB];     // partial attention logits per e-tile
__device__ float g_attn[TT * BB];
__device__ float g_vec[BB][DD2];
__device__ float g_dummy[32];

// per-group barrier state: 8 groups of 8 CTAs
__device__ unsigned g_cnt[8];            // zero-init, returns to 0 every barrier
__device__ unsigned g_flag[8];           // zero-init, monotonically increasing (replay-safe)

// ---------------- packed f32x2 helpers (sm_100+) ----------------
__device__ __forceinline__ ULL pk(float lo, float hi) {
    ULL r; asm("mov.b64 %0,{%1,%2};" : "=l"(r) : "f"(lo), "f"(hi)); return r;
}
__device__ __forceinline__ ULL pk2(float x) {
    ULL r; asm("mov.b64 %0,{%1,%1};" : "=l"(r) : "f"(x)); return r;
}
__device__ __forceinline__ void fma2(ULL& d, ULL a, ULL b) {
    asm("fma.rn.f32x2 %0,%1,%2,%0;" : "+l"(d) : "l"(a), "l"(b));
}
__device__ __forceinline__ ULL add2(ULL a, ULL b) {
    ULL r; asm("add.rn.f32x2 %0,%1,%2;" : "=l"(r) : "l"(a), "l"(b)); return r;
}
__device__ __forceinline__ float2 upk(ULL v) {
    float2 r; asm("mov.b64 {%0,%1},%2;" : "=f"(r.x), "=f"(r.y) : "l"(v)); return r;
}

// fast (still ~1e-6-accurate) gate nonlinearities
__device__ __forceinline__ float sig_f(float x) {
    return __fdividef(1.0f, 1.0f + __expf(-x));
}
__device__ __forceinline__ float tanh_f(float x) {
    return __fdividef(2.0f, 1.0f + __expf(-2.0f * x)) - 1.0f;
}

// ---------------- acquire/release global sync primitives ----------------
__device__ __forceinline__ unsigned ld_acq(const unsigned* p) {
    unsigned v;
    asm volatile("ld.acquire.gpu.global.u32 %0,[%1];" : "=r"(v) : "l"(p) : "memory");
    return v;
}
__device__ __forceinline__ void st_rel(unsigned* p, unsigned v) {
    asm volatile("st.release.gpu.global.u32 [%0],%1;" :: "l"(p), "r"(v) : "memory");
}
__device__ __forceinline__ unsigned atom_add_acqrel(unsigned* p, unsigned v) {
    unsigned o;
    asm volatile("atom.acq_rel.gpu.global.add.u32 %0,[%1],%2;" : "=r"(o) : "l"(p), "r"(v) : "memory");
    return o;
}

// sense-reversing barrier over the 8 CTAs of group gidx (no fence, no nanosleep)
__device__ __forceinline__ void group_sync(int gidx) {
    __syncthreads();                     // all threads' work done before leader arrives
    if (threadIdx.x == 0) {
        unsigned ph = ld_acq(&g_flag[gidx]);           // stable: can't advance w/o our arrive
        if (atom_add_acqrel(&g_cnt[gidx], 1u) == 7u) { // acq_rel: sees peers' released stores
            g_cnt[gidx] = 0u;                          // ordered before flag by release below
            st_rel(&g_flag[gidx], ph + 1u);
        } else {
            while (ld_acq(&g_flag[gidx]) == ph) { }    // tight poll, ~L2 latency granularity
        }
    }
    __syncthreads();                     // distribute acquired visibility to all threads
}

// =====================================================================
// K1: xg[d][t][g][b] = Wih_d @ emb_table[embed[t]]^T + bih + bhh
// one launch per direction; grid (8 gate-tiles, T), 256 thr, tile 128x64
// =====================================================================
__global__ void __launch_bounds__(256) k1_xg(
    int d, const int* __restrict__ embed, const float* __restrict__ emb_table,
    const float* __restrict__ Wih, const float* __restrict__ bi, const float* __restrict__ bh)
{
    const int gt = blockIdx.x;
    const int t  = blockIdx.y;

    __shared__ float A[32][132];   // [k][row]
    __shared__ float X[32][64];    // [k][b]
    __shared__ int   idx[64];

    const int tid = threadIdx.x;
    if (tid < 64) idx[tid] = embed[t * BB + tid];

    const int g0 = gt * 128;
    const int ty = tid >> 4;   // 0..15 -> 8 rows at ty*8
    const int tx = tid & 15;   // 0..15 -> 4 batches at tx*4

    ULL acc[4][4];
#pragma unroll
    for (int gp = 0; gp < 4; gp++) {
        int r = g0 + ty * 8 + gp * 2;
        ULL bbv = pk(bi[r] + bh[r], bi[r + 1] + bh[r + 1]);
#pragma unroll
        for (int j = 0; j < 4; j++) acc[gp][j] = bbv;
    }

    for (int kt = 0; kt < 8; kt++) {
        const int k0 = kt * 32;
        __syncthreads();
        {   // W tile -> A[k][r] (transposed)
            int r  = tid >> 1;
            int kk = (tid & 1) * 16;
            const float4* src = (const float4*)(Wih + (g0 + r) * EE + k0 + kk);
#pragma unroll
            for (int qq = 0; qq < 4; qq++) {
                float4 v = src[qq];
                A[kk + qq * 4 + 0][r] = v.x;
                A[kk + qq * 4 + 1][r] = v.y;
                A[kk + qq * 4 + 2][r] = v.z;
                A[kk + qq * 4 + 3][r] = v.w;
            }
        }
        {   // X tile: gather embeddings -> X[k][b]
            int b  = tid >> 2;
            int kk = (tid & 3) * 8;
            const float* er = emb_table + (long long)idx[b] * EE + k0 + kk;
            float4 v0 = *(const float4*)(er);
            float4 v1 = *(const float4*)(er + 4);
            X[kk + 0][b] = v0.x; X[kk + 1][b] = v0.y; X[kk + 2][b] = v0.z; X[kk + 3][b] = v0.w;
            X[kk + 4][b] = v1.x; X[kk + 5][b] = v1.y; X[kk + 6][b] = v1.z; X[kk + 7][b] = v1.w;
        }
        __syncthreads();
#pragma unroll
        for (int k = 0; k < 32; k++) {
            float4 w0 = *(const float4*)&A[k][ty * 8];
            float4 w1 = *(const float4*)&A[k][ty * 8 + 4];
            ULL wp0 = pk(w0.x, w0.y), wp1 = pk(w0.z, w0.w);
            ULL wp2 = pk(w1.x, w1.y), wp3 = pk(w1.z, w1.w);
            float4 xv = *(const float4*)&X[k][tx * 4];
            ULL x0 = pk2(xv.x), x1 = pk2(xv.y), x2 = pk2(xv.z), x3 = pk2(xv.w);
            fma2(acc[0][0], wp0, x0); fma2(acc[0][1], wp0, x1); fma2(acc[0][2], wp0, x2); fma2(acc[0][3], wp0, x3);
            fma2(acc[1][0], wp1, x0); fma2(acc[1][1], wp1, x1); fma2(acc[1][2], wp1, x2); fma2(acc[1][3], wp1, x3);
            fma2(acc[2][0], wp2, x0); fma2(acc[2][1], wp2, x1); fma2(acc[2][2], wp2, x2); fma2(acc[2][3], wp2, x3);
            fma2(acc[3][0], wp3, x0); fma2(acc[3][1], wp3, x1); fma2(acc[3][2], wp3, x2); fma2(acc[3][3], wp3, x3);
        }
    }

    float* dst = &g_xg[d][t][0][0];
#pragma unroll
    for (int gp = 0; gp < 4; gp++) {
        int r = g0 + ty * 8 + gp * 2;
        float2 a0 = upk(acc[gp][0]), a1 = upk(acc[gp][1]), a2 = upk(acc[gp][2]), a3 = upk(acc[gp][3]);
        __stcs((float4*)&dst[r * BB + tx * 4],       make_float4(a0.x, a1.x, a2.x, a3.x));
        __stcs((float4*)&dst[(r + 1) * BB + tx * 4], make_float4(a0.y, a1.y, a2.y, a3.y));
    }
}

// pad kernel (keeps K2 at captured launch index 3)
__global__ void k_pad() { if (threadIdx.x == 0) g_dummy[0] = 0.f; }

// =====================================================================
// K2: persistent biLSTM recurrence, NO clusters, 64 CTAs (co-residency-safe).
// 64 CTAs = 2 dirs x 4 batch-groups(16 batches) x 8 hidden-groups(32 hidden).
// The 8 CTAs sharing (dir,bg) sync via a private acq/rel atomic barrier.
// Whh slice register-resident: thread = (gate-row r in [0,128), k-quarter q),
// w[64] = row grow, k in [q*64,(q+1)*64). 8 f32x2 accs = 16 batches.
// =====================================================================
constexpr int HQ = 1028;                   // padded quarter stride (floats)

__global__ void __launch_bounds__(512, 1)
k2_rnn(const float* __restrict__ h0, const float* __restrict__ c0,
       const float* __restrict__ Whh_f, const float* __restrict__ Whh_b)
{
    __shared__ __align__(16) float h_sm[4 * HQ]; // 4 padded k-quarters of [k][bl=16]
    __shared__ float gsm[2048];                  // [gate][jl][bl] 8KB
    __shared__ float csm[512];                   // [jl][bl] 2KB

    const int bid = blockIdx.x;                  // 0..63
    const int hg = bid & 7;
    const int bg = (bid >> 3) & 3;
    const int d  = bid >> 5;
    const int gid = bid >> 3;                    // group 0..7
    const int tid = threadIdx.x;
    const int r = tid >> 2, q = tid & 3;         // r: gate-row in CTA, q: k-quarter
    const int gate = r >> 5, jl = r & 31;
    const int grow = gate * 256 + hg * 32 + jl;  // global gate-row
    const float* Whh = d ? Whh_b : Whh_f;

    // register-resident Whh slice
    float w[64];
    {
        const float4* ws = (const float4*)(Whh + grow * HH + q * 64);
#pragma unroll
        for (int i = 0; i < 16; i++) {
            float4 v = ws[i];
            w[4 * i] = v.x; w[4 * i + 1] = v.y; w[4 * i + 2] = v.z; w[4 * i + 3] = v.w;
        }
    }

    {   // init state: 512 threads = 32 jl x 16 bl
        int cj = tid >> 4, cb = tid & 15;
        int b = bg * 16 + cb, j = hg * 32 + cj;
        csm[cj * 16 + cb] = c0[(d * BB + b) * HH + j];
        __stcg(&g_h[0][d][bg][j][cb], h0[(d * BB + b) * HH + j]);
    }
    group_sync(gid);

    int p = 0;
    for (int s = 0; s < TT; s++) {
        const int t = d ? (TT - 1 - s) : s;

        // xg prefetch: lane q loads its 4 batches of this row (streaming)
        float4 xv = __ldcs((const float4*)&g_xg[d][t][grow][bg * 16] + q);

        {   // stage h_prev (16 KB) into padded smem quarters (L2 -> smem)
            const float4* hs = (const float4*)&g_h[p][d][bg][0][0];
#pragma unroll
            for (int i = 0; i < 2; i++) {
                int v4 = tid + i * 512;              // float4 index, 0..1023
                int f  = v4 * 4;                     // source float index
                float4 val = __ldcg(hs + v4);
                *(float4*)&h_sm[(f >> 10) * HQ + (f & 1023)] = val;
            }
        }
        __syncthreads();

        ULL acc[8];
#pragma unroll
        for (int i = 0; i < 8; i++) acc[i] = 0ull;

        const ulonglong2* hb = (const ulonglong2*)(h_sm + q * HQ);
#pragma unroll 8
        for (int k = 0; k < 64; k++) {
            ULL w2 = pk2(w[k]);
            ulonglong2 hA = hb[4 * k + 0], hB = hb[4 * k + 1];
            ulonglong2 hC = hb[4 * k + 2], hD = hb[4 * k + 3];
            fma2(acc[0], w2, hA.x); fma2(acc[1], w2, hA.y);
            fma2(acc[2], w2, hB.x); fma2(acc[3], w2, hB.y);
            fma2(acc[4], w2, hC.x); fma2(acc[5], w2, hC.y);
            fma2(acc[6], w2, hD.x); fma2(acc[7], w2, hD.y);
        }
        // reduce across the 4 k-quarter lanes (same r: lanes xor 1, 2)
#pragma unroll
        for (int i = 0; i < 8; i++) {
            acc[i] = add2(acc[i], __shfl_xor_sync(0xffffffffu, acc[i], 1));
            acc[i] = add2(acc[i], __shfl_xor_sync(0xffffffffu, acc[i], 2));
        }
        // lane q owns batches [4q,4q+4): add its xg, store to gsm
        {
            float2 p0 = upk(acc[2 * q]), p1 = upk(acc[2 * q + 1]);
            *(float4*)&gsm[gate * 512 + jl * 16 + q * 4] =
                make_float4(p0.x + xv.x, p0.y + xv.y, p1.x + xv.z, p1.y + xv.w);
        }
        __syncthreads();

        {   // tail: all 512 threads, one (j,b) each
            int cj = tid >> 4, cb = tid & 15;
            int o = cj * 16 + cb;
            float gi = gsm[o];
            float gf = gsm[512 + o];
            float gg = gsm[1024 + o];
            float go = gsm[1536 + o];
            float c = csm[o];
            c = sig_f(gf) * c + sig_f(gi) * tanh_f(gg);
            float h = sig_f(go) * tanh_f(c);
            csm[o] = c;
            __stcg(&g_h[p ^ 1][d][bg][hg * 32 + cj][cb], h);
            g_out[t][d * 256 + hg * 32 + cj][bg * 16 + cb] = h;
        }
        group_sync(gid);
        p ^= 1;
    }
}

// =====================================================================
// K3a: partial attention logits.
// plog[et][t][b] = sum_{e in tile} tanh((out[t,b,:]@W_word)[e]+b_word[e])*proj[e]
// grid (4 e-tiles, T), tile 128x64, K=512
// =====================================================================
__global__ void __launch_bounds__(256) k3a_logits(
    const float* __restrict__ W_word, const float* __restrict__ b_word,
    const float* __restrict__ proj)
{
    const int et = blockIdx.x;
    const int t  = blockIdx.y;
    __shared__ float Bs[32][132];   // [k][e]
    __shared__ float Xs[32][64];    // [k][b]
    __shared__ float red[64][17];

    const int tid = threadIdx.x;
    const int ty = tid >> 4, tx = tid & 15;
    const int e0 = et * 128;

    ULL acc[4][4];
#pragma unroll
    for (int gp = 0; gp < 4; gp++)
#pragma unroll
        for (int j = 0; j < 4; j++) acc[gp][j] = 0ull;

    for (int kt = 0; kt < 16; kt++) {
        const int k0 = kt * 32;
        __syncthreads();
        {   // W_word tile (already [d][e] = [k][e], no transpose)
            int k  = tid >> 3;
            int ec = (tid & 7) * 16;
            const float4* src = (const float4*)(W_word + (k0 + k) * DD2 + e0 + ec);
#pragma unroll
            for (int qq = 0; qq < 4; qq++)
                *(float4*)&Bs[k][ec + qq * 4] = src[qq];
        }
        {   // out tile: g_out[t][k][b], b contiguous
            int k  = tid >> 3;
            int bc = (tid & 7) * 8;
            const float4* src = (const float4*)&g_out[t][k0 + k][bc];
            *(float4*)&Xs[k][bc]     = src[0];
            *(float4*)&Xs[k][bc + 4] = src[1];
        }
        __syncthreads();
#pragma unroll
        for (int k = 0; k < 32; k++) {
            float4 w0 = *(const float4*)&Bs[k][ty * 8];
            float4 w1 = *(const float4*)&Bs[k][ty * 8 + 4];
            ULL wp0 = pk(w0.x, w0.y), wp1 = pk(w0.z, w0.w);
            ULL wp2 = pk(w1.x, w1.y), wp3 = pk(w1.z, w1.w);
            float4 xv = *(const float4*)&Xs[k][tx * 4];
            ULL x0 = pk2(xv.x), x1 = pk2(xv.y), x2 = pk2(xv.z), x3 = pk2(xv.w);
            fma2(acc[0][0], wp0, x0); fma2(acc[0][1], wp0, x1); fma2(acc[0][2], wp0, x2); fma2(acc[0][3], wp0, x3);
            fma2(acc[1][0], wp1, x0); fma2(acc[1][1], wp1, x1); fma2(acc[1][2], wp1, x2); fma2(acc[1][3], wp1, x3);
            fma2(acc[2][0], wp2, x0); fma2(acc[2][1], wp2, x1); fma2(acc[2][2], wp2, x2); fma2(acc[2][3], wp2, x3);
            fma2(acc[3][0], wp3, x0); fma2(acc[3][1], wp3, x1); fma2(acc[3][2], wp3, x2); fma2(acc[3][3], wp3, x3);
        }
    }

    // finalize: tanh(+bias)*proj, reduce over this thread's 8 e-rows
    float part[4] = {0.f, 0.f, 0.f, 0.f};
#pragma unroll
    for (int gp = 0; gp < 4; gp++) {
        int e = e0 + ty * 8 + gp * 2;
        float bw0 = b_word[e], bw1 = b_word[e + 1];
        float pw0 = proj[e],   pw1 = proj[e + 1];
#pragma unroll
        for (int j = 0; j < 4; j++) {
            float2 a = upk(acc[gp][j]);
            part[j] += tanh_f(a.x + bw0) * pw0 + tanh_f(a.y + bw1) * pw1;
        }
    }
#pragma unroll
    for (int j = 0; j < 4; j++) red[tx * 4 + j][ty] = part[j];
    __syncthreads();
    if (tid < 64) {
        float s = 0.f;
#pragma unroll
        for (int i = 0; i < 16; i++) s += red[tid][i];
        g_plog[et][t * BB + tid] = s;
    }
}

// =====================================================================
// K3b1: softmax over T per batch. One CTA per batch (64 CTAs, 256 thr).
// =====================================================================
__global__ void __launch_bounds__(256) k3b1_softmax()
{
    __shared__ float red[8];
    const int b = blockIdx.x;
    const int tid = threadIdx.x;
    const int wid = tid >> 5, lane = tid & 31;

    const int o0 = tid * BB + b, o1 = (tid + 256) * BB + b;
    float l0 = g_plog[0][o0] + g_plog[1][o0] + g_plog[2][o0] + g_plog[3][o0];
    float l1 = g_plog[0][o1] + g_plog[1][o1] + g_plog[2][o1] + g_plog[3][o1];

    float m = fmaxf(l0, l1);
#pragma unroll
    for (int off = 16; off; off >>= 1) m = fmaxf(m, __shfl_xor_sync(0xffffffffu, m, off));
    if (lane == 0) red[wid] = m;
    __syncthreads();
    m = red[0];
#pragma unroll
    for (int i = 1; i < 8; i++) m = fmaxf(m, red[i]);
    __syncthreads();

    float e0 = expf(l0 - m), e1 = expf(l1 - m);
    float s = e0 + e1;
#pragma unroll
    for (int off = 16; off; off >>= 1) s += __shfl_xor_sync(0xffffffffu, s, off);
    if (lane == 0) red[wid] = s;
    __syncthreads();
    s = red[0] + red[1] + red[2] + red[3] + red[4] + red[5] + red[6] + red[7];
    float inv = 1.0f / s;

    g_attn[o0] = e0 * inv;
    g_attn[o1] = e1 * inv;
}

// =====================================================================
// K3b2: vec[b][d] = sum_t attn[t,b] * out[t,d,b]   (64 CTAs x 8 d-rows)
// =====================================================================
__global__ void __launch_bounds__(256) k3b2_vec()
{
    const int d0 = blockIdx.x * 8;
    const int dl = threadIdx.x >> 5, lane = threadIdx.x & 31;
    const int row = d0 + dl;
    float a0 = 0.f, a1 = 0.f;
#pragma unroll 4
    for (int t = 0; t < TT; t++) {
        float at0 = g_attn[t * BB + lane];
        float at1 = g_attn[t * BB + 32 + lane];
        a0 += at0 * g_out[t][row][lane];
        a1 += at1 * g_out[t][row][32 + lane];
    }
    g_vec[lane][row] = a0;
    g_vec[32 + lane][row] = a1;
}

// =====================================================================
// K3c: final linear  out[b][n] = vec[b,:] . lin_W[n,:] + lin_b[n]
// =====================================================================
__global__ void __launch_bounds__(512) k3c_final(
    const float* __restrict__ lin_W, const float* __restrict__ lin_b,
    float* __restrict__ out)
{
    const int wid = threadIdx.x >> 5, lane = threadIdx.x & 31;
    for (int i = 0; i < 20; i++) {
        int o = wid * 20 + i;           // 16 warps * 20 = 320 outputs
        int b = o / NCLS, n = o % NCLS;
        float s = 0.f;
#pragma unroll
        for (int j = 0; j < 16; j++) {
            int dd = lane + 32 * j;
            s += g_vec[b][dd] * lin_W[n * DD2 + dd];
        }
#pragma unroll
        for (int off = 16; off; off >>= 1)
            s += __shfl_xor_sync(0xffffffffu, s, off);
        if (lane == 0) out[b * NCLS + n] = s + lin_b[n];
    }
}

// =====================================================================
extern "C" void kernel_launch(void* const* d_in, const int* in_sizes, int n_in,
                              void* d_out, int out_size)
{
    const int*   embed     = (const int*)  d_in[0];
    const float* h0        = (const float*)d_in[1];
    const float* c0        = (const float*)d_in[2];
    const float* emb_table = (const float*)d_in[3];
    const float* Wih_f     = (const float*)d_in[4];
    const float* Whh_f     = (const float*)d_in[5];
    const float* bih_f     = (const float*)d_in[6];
    const float* bhh_f     = (const float*)d_in[7];
    const float* Wih_b     = (const float*)d_in[8];
    const float* Whh_b     = (const float*)d_in[9];
    const float* bih_b     = (const float*)d_in[10];
    const float* bhh_b     = (const float*)d_in[11];
    const float* W_word    = (const float*)d_in[12];
    const float* b_word    = (const float*)d_in[13];
    const float* proj_word = (const float*)d_in[14];
    const float* lin_W     = (const float*)d_in[15];
    const float* lin_b     = (const float*)d_in[16];
    float* out = (float*)d_out;

    k1_xg<<<dim3(8, TT), 256>>>(0, embed, emb_table, Wih_f, bih_f, bhh_f);   // idx 0
    k1_xg<<<dim3(8, TT), 256>>>(1, embed, emb_table, Wih_b, bih_b, bhh_b);   // idx 1
    k_pad<<<1, 32>>>();                                                      // idx 2
    k2_rnn<<<64, 512>>>(h0, c0, Whh_f, Whh_b);                               // idx 3 (capture slot)
    k3a_logits<<<dim3(4, TT), 256>>>(W_word, b_word, proj_word);             // idx 4
    k3b1_softmax<<<64, 256>>>();                                             // idx 5
    k3b2_vec<<<64, 256>>>();                                                 // idx 6
    k3c_final<<<1, 512>>>(lin_W, lin_b, out);                                // idx 7
}